// round 1
// baseline (speedup 1.0000x reference)
#include <cuda_runtime.h>
#include <math.h>

#define SDIM 4096
#define BDIM 4096
#define NTILE 32              // SDIM / BN partial tiles

// scratch (static __device__ arrays: allowed; no runtime allocation)
__device__ float g_c[SDIM];
__device__ float g_d[SDIM];
__device__ float g_partial[(size_t)BDIM * NTILE];

__device__ __forceinline__ float gelu_exact(float x) {
    return 0.5f * x * (1.0f + erff(x * 0.70710678118654752f));
}

__device__ __forceinline__ float block_reduce_sum(float v, float* sbuf) {
    int lane = threadIdx.x & 31;
    int warp = threadIdx.x >> 5;
    #pragma unroll
    for (int o = 16; o > 0; o >>= 1) v += __shfl_down_sync(0xffffffffu, v, o);
    if (lane == 0) sbuf[warp] = v;
    __syncthreads();
    if (warp == 0) {
        v = (lane < ((int)blockDim.x >> 5)) ? sbuf[lane] : 0.0f;
        #pragma unroll
        for (int o = 16; o > 0; o >>= 1) v += __shfl_down_sync(0xffffffffu, v, o);
    }
    return v;  // valid in thread 0
}

// c[s] = sum_i ( Gu_i * (sgu_ln_b[i]*rowsum_i[s] + sgu_proj_b[i][s]) * cp2_w[i] + cp2_b[i] )
__global__ void compute_c_kernel(const float* __restrict__ sgu_proj_w,
                                 const float* __restrict__ sgu_proj_b,
                                 const float* __restrict__ ln1_b,
                                 const float* __restrict__ cp1_w,
                                 const float* __restrict__ cp1_b,
                                 const float* __restrict__ sgu_ln_b,
                                 const float* __restrict__ cp2_w,
                                 const float* __restrict__ cp2_b) {
    __shared__ float sbuf[8];
    int s = blockIdx.x;
    float total = 0.0f;
    #pragma unroll
    for (int i = 0; i < 2; ++i) {
        const float* row = sgu_proj_w + (size_t)i * SDIM * SDIM + (size_t)s * SDIM;
        float acc = 0.0f;
        for (int t = threadIdx.x; t < SDIM; t += blockDim.x) acc += row[t];
        float rowsum = block_reduce_sum(acc, sbuf);
        if (threadIdx.x == 0) {
            // layernorm over size-1 axis == bias
            float tln    = ln1_b[i];
            float Gu     = gelu_exact(tln * cp1_w[i * 2 + 0] + cp1_b[i * 2 + 0]);
            float vconst = sgu_ln_b[i];
            float vp     = vconst * rowsum + sgu_proj_b[(size_t)i * SDIM + s];
            total += (Gu * vp) * cp2_w[i] + cp2_b[i];
        }
        __syncthreads();  // sbuf reuse between layers
    }
    if (threadIdx.x == 0) g_c[s] = total;
}

// d[s'] = sum_s c[s] * pooler_w[s', s] + pooler_b[s']
__global__ void compute_d_kernel(const float* __restrict__ pooler_w,
                                 const float* __restrict__ pooler_b) {
    __shared__ float sbuf[8];
    int sp = blockIdx.x;
    const float* row = pooler_w + (size_t)sp * SDIM;
    float acc = 0.0f;
    for (int t = threadIdx.x; t < SDIM; t += blockDim.x) acc += row[t] * g_c[t];
    float v = block_reduce_sum(acc, sbuf);
    if (threadIdx.x == 0) g_d[sp] = v + pooler_b[sp];
}

// Fused:  y = x @ pooler_w^T ; out = gelu(y + d) ; partial[b][tileS] = sum_{s' in tile} out * cls_w[s']
#define BM 128
#define BN 128
#define BK 16
__global__ void __launch_bounds__(256, 2)
gemm_fused_kernel(const float* __restrict__ A,   // x   (B, S) row-major
                  const float* __restrict__ W,   // pooler_w (S', S) row-major  (NT: both K-contiguous)
                  const float* __restrict__ clsw) {
    __shared__ float As[BK][BM];
    __shared__ float Bs[BK][BN];
    __shared__ float red[BM][17];

    const int tid = threadIdx.x;
    const int tx = tid & 15;   // -> s' micro
    const int ty = tid >> 4;   // -> b  micro
    const int bB = blockIdx.y * BM;
    const int bS = blockIdx.x * BN;

    float acc[8][8];
    #pragma unroll
    for (int m = 0; m < 8; ++m)
        #pragma unroll
        for (int n = 0; n < 8; ++n) acc[m][n] = 0.0f;

    const int lrow = tid >> 2;        // 0..63
    const int lc4  = (tid & 3) * 4;   // 0,4,8,12

    const float* Aptr = A + (size_t)bB * SDIM;
    const float* Wptr = W + (size_t)bS * SDIM;

    for (int k0 = 0; k0 < SDIM; k0 += BK) {
        float4 a0 = *(const float4*)(Aptr + (size_t)lrow        * SDIM + k0 + lc4);
        float4 a1 = *(const float4*)(Aptr + (size_t)(lrow + 64) * SDIM + k0 + lc4);
        float4 b0 = *(const float4*)(Wptr + (size_t)lrow        * SDIM + k0 + lc4);
        float4 b1 = *(const float4*)(Wptr + (size_t)(lrow + 64) * SDIM + k0 + lc4);
        __syncthreads();  // previous iteration's smem reads complete
        As[lc4 + 0][lrow] = a0.x; As[lc4 + 1][lrow] = a0.y;
        As[lc4 + 2][lrow] = a0.z; As[lc4 + 3][lrow] = a0.w;
        As[lc4 + 0][lrow + 64] = a1.x; As[lc4 + 1][lrow + 64] = a1.y;
        As[lc4 + 2][lrow + 64] = a1.z; As[lc4 + 3][lrow + 64] = a1.w;
        Bs[lc4 + 0][lrow] = b0.x; Bs[lc4 + 1][lrow] = b0.y;
        Bs[lc4 + 2][lrow] = b0.z; Bs[lc4 + 3][lrow] = b0.w;
        Bs[lc4 + 0][lrow + 64] = b1.x; Bs[lc4 + 1][lrow + 64] = b1.y;
        Bs[lc4 + 2][lrow + 64] = b1.z; Bs[lc4 + 3][lrow + 64] = b1.w;
        __syncthreads();
        #pragma unroll
        for (int kk = 0; kk < BK; ++kk) {
            float a[8], b[8];
            *(float4*)&a[0] = *(const float4*)&As[kk][ty * 8];
            *(float4*)&a[4] = *(const float4*)&As[kk][ty * 8 + 4];
            *(float4*)&b[0] = *(const float4*)&Bs[kk][tx * 8];
            *(float4*)&b[4] = *(const float4*)&Bs[kk][tx * 8 + 4];
            #pragma unroll
            for (int m = 0; m < 8; ++m)
                #pragma unroll
                for (int n = 0; n < 8; ++n) acc[m][n] += a[m] * b[n];
        }
    }

    // epilogue: +d, gelu, *cls_w, reduce over s' within tile
    float dreg[8], wreg[8];
    #pragma unroll
    for (int n = 0; n < 8; ++n) {
        int sp = bS + tx * 8 + n;
        dreg[n] = g_d[sp];
        wreg[n] = clsw[sp];
    }
    float p[8];
    #pragma unroll
    for (int m = 0; m < 8; ++m) {
        float sum = 0.0f;
        #pragma unroll
        for (int n = 0; n < 8; ++n) {
            float y = acc[m][n] + dreg[n];
            sum += gelu_exact(y) * wreg[n];
        }
        p[m] = sum;
    }
    #pragma unroll
    for (int m = 0; m < 8; ++m) red[ty * 8 + m][tx] = p[m];
    __syncthreads();
    if (tid < 128) {
        float sum = 0.0f;
        #pragma unroll
        for (int j = 0; j < 16; ++j) sum += red[tid][j];
        g_partial[(size_t)(bB + tid) * NTILE + blockIdx.x] = sum;
    }
}

__global__ void final_kernel(const float* __restrict__ cls_b, float* __restrict__ out) {
    int b = blockIdx.x * blockDim.x + threadIdx.x;
    if (b < BDIM) {
        float sum = 0.0f;
        #pragma unroll
        for (int j = 0; j < NTILE; ++j) sum += g_partial[(size_t)b * NTILE + j];
        out[b] = sum + cls_b[0];
    }
}

extern "C" void kernel_launch(void* const* d_in, const int* in_sizes, int n_in,
                              void* d_out, int out_size) {
    const float* x          = (const float*)d_in[0];
    const float* ln1_b      = (const float*)d_in[2];
    const float* cp1_w      = (const float*)d_in[3];
    const float* cp1_b      = (const float*)d_in[4];
    const float* sgu_ln_b   = (const float*)d_in[6];
    const float* sgu_proj_w = (const float*)d_in[7];
    const float* sgu_proj_b = (const float*)d_in[8];
    const float* cp2_w      = (const float*)d_in[9];
    const float* cp2_b      = (const float*)d_in[10];
    const float* pooler_w   = (const float*)d_in[11];
    const float* pooler_b   = (const float*)d_in[12];
    const float* cls_w      = (const float*)d_in[13];
    const float* cls_b      = (const float*)d_in[14];

    compute_c_kernel<<<SDIM, 256>>>(sgu_proj_w, sgu_proj_b, ln1_b, cp1_w, cp1_b,
                                    sgu_ln_b, cp2_w, cp2_b);
    compute_d_kernel<<<SDIM, 256>>>(pooler_w, pooler_b);

    dim3 grid(SDIM / BN, BDIM / BM);
    gemm_fused_kernel<<<grid, 256>>>(x, pooler_w, cls_w);

    final_kernel<<<(BDIM + 255) / 256, 256>>>(cls_b, (float*)d_out);
}

// round 3
// speedup vs baseline: 2.8449x; 2.8449x over previous
#include <cuda_runtime.h>
#include <cuda_bf16.h>
#include <math.h>
#include <stdint.h>

#define SDIM 4096
#define BDIM 4096
#define BM 128
#define BN 128
#define BK 16
#define NCH (SDIM / BK)      // 256
#define NTILE (SDIM / BN)    // 32

// ---------------- scratch ----------------
__device__ float g_c[SDIM];
__device__ float g_d[SDIM];
__device__ float g_partial[(size_t)BDIM * NTILE];

// ---------------- helpers ----------------
__device__ __forceinline__ float gelu_exact(float x) {
    return 0.5f * x * (1.0f + erff(x * 0.70710678118654752f));
}

__device__ __forceinline__ uint32_t smem_u32(const void* p) {
    uint32_t a;
    asm("{ .reg .u64 t; cvta.to.shared.u64 t, %1; cvt.u32.u64 %0, t; }" : "=r"(a) : "l"(p));
    return a;
}

// swizzle for 32B rows: XOR bit4 with bit7  (8-row period, conflict-free ldmatrix)
__device__ __host__ __forceinline__ uint32_t swz(uint32_t off) {
    return off ^ ((off >> 3) & 0x10);
}

__device__ __forceinline__ uint32_t prmt_hi(uint32_t x, uint32_t y) {
    uint32_t r;
    asm("prmt.b32 %0, %1, %2, 0x7632;" : "=r"(r) : "r"(x), "r"(y));
    return r;  // {hi16(x), hi16(y)} packed: x in low half
}

__device__ __forceinline__ uint32_t cvt_bf16x2(float hi, float lo) {
    uint32_t r;
    asm("cvt.rn.bf16x2.f32 %0, %1, %2;" : "=r"(r) : "f"(hi), "f"(lo));
    return r;  // lo in low half
}

#define LDSM_X4(r0, r1, r2, r3, addr) \
    asm volatile("ldmatrix.sync.aligned.m8n8.x4.shared.b16 {%0,%1,%2,%3}, [%4];" \
        : "=r"(r0), "=r"(r1), "=r"(r2), "=r"(r3) : "r"(addr))

__device__ __forceinline__ void mma16816(float* c, uint32_t a0, uint32_t a1, uint32_t a2, uint32_t a3,
                                         uint32_t b0, uint32_t b1) {
    asm volatile("mma.sync.aligned.m16n8k16.row.col.f32.bf16.bf16.f32 "
        "{%0,%1,%2,%3}, {%4,%5,%6,%7}, {%8,%9}, {%0,%1,%2,%3};"
        : "+f"(c[0]), "+f"(c[1]), "+f"(c[2]), "+f"(c[3])
        : "r"(a0), "r"(a1), "r"(a2), "r"(a3), "r"(b0), "r"(b1));
}

// split fp32 -> (hi bf16 by truncation, lo bf16 = rn(x - hi)); x - hi is exact.
__device__ __forceinline__ void split_store(char* hbase, char* lbase, uint32_t off, float4 v) {
    uint32_t ux = __float_as_uint(v.x), uy = __float_as_uint(v.y);
    uint32_t uz = __float_as_uint(v.z), uw = __float_as_uint(v.w);
    uint32_t h0 = prmt_hi(ux, uy);
    uint32_t h1 = prmt_hi(uz, uw);
    float lx = v.x - __uint_as_float(ux & 0xffff0000u);
    float ly = v.y - __uint_as_float(uy & 0xffff0000u);
    float lz = v.z - __uint_as_float(uz & 0xffff0000u);
    float lw = v.w - __uint_as_float(uw & 0xffff0000u);
    uint32_t l0 = cvt_bf16x2(ly, lx);
    uint32_t l1 = cvt_bf16x2(lw, lz);
    *(uint2*)(hbase + off) = make_uint2(h0, h1);
    *(uint2*)(lbase + off) = make_uint2(l0, l1);
}

// ---------------- prologue kernels ----------------
__device__ __forceinline__ float block_reduce_sum(float v, float* sbuf) {
    int lane = threadIdx.x & 31, warp = threadIdx.x >> 5;
    #pragma unroll
    for (int o = 16; o > 0; o >>= 1) v += __shfl_down_sync(0xffffffffu, v, o);
    if (lane == 0) sbuf[warp] = v;
    __syncthreads();
    if (warp == 0) {
        v = (lane < ((int)blockDim.x >> 5)) ? sbuf[lane] : 0.0f;
        #pragma unroll
        for (int o = 16; o > 0; o >>= 1) v += __shfl_down_sync(0xffffffffu, v, o);
    }
    return v;
}

__global__ void compute_c_kernel(const float* __restrict__ sgu_proj_w,
                                 const float* __restrict__ sgu_proj_b,
                                 const float* __restrict__ ln1_b,
                                 const float* __restrict__ cp1_w,
                                 const float* __restrict__ cp1_b,
                                 const float* __restrict__ sgu_ln_b,
                                 const float* __restrict__ cp2_w,
                                 const float* __restrict__ cp2_b) {
    __shared__ float sbuf[8];
    int s = blockIdx.x;
    float total = 0.0f;
    #pragma unroll
    for (int i = 0; i < 2; ++i) {
        const float* row = sgu_proj_w + (size_t)i * SDIM * SDIM + (size_t)s * SDIM;
        float acc = 0.0f;
        for (int t = threadIdx.x * 4; t < SDIM; t += blockDim.x * 4) {
            float4 v = *(const float4*)(row + t);
            acc += (v.x + v.y) + (v.z + v.w);
        }
        float rowsum = block_reduce_sum(acc, sbuf);
        if (threadIdx.x == 0) {
            float tln = ln1_b[i];  // LN over size-1 axis == bias
            float Gu  = gelu_exact(tln * cp1_w[i * 2 + 0] + cp1_b[i * 2 + 0]);
            float vp  = sgu_ln_b[i] * rowsum + sgu_proj_b[(size_t)i * SDIM + s];
            total += (Gu * vp) * cp2_w[i] + cp2_b[i];
        }
        __syncthreads();
    }
    if (threadIdx.x == 0) g_c[s] = total;
}

__global__ void compute_d_kernel(const float* __restrict__ pooler_w,
                                 const float* __restrict__ pooler_b) {
    __shared__ float sbuf[8];
    int sp = blockIdx.x;
    const float* row = pooler_w + (size_t)sp * SDIM;
    float acc = 0.0f;
    for (int t = threadIdx.x * 4; t < SDIM; t += blockDim.x * 4) {
        float4 v = *(const float4*)(row + t);
        acc += v.x * g_c[t] + v.y * g_c[t + 1] + v.z * g_c[t + 2] + v.w * g_c[t + 3];
    }
    float v = block_reduce_sum(acc, sbuf);
    if (threadIdx.x == 0) g_d[sp] = v + pooler_b[sp];
}

// ---------------- bf16 3-split tensor-core GEMM with fused epilogue ----------------
// SMEM stage layout (16KB/stage, 2 stages = 32KB static):
//   +0     A_hi  128 rows x 32B
//   +4096  A_lo
//   +8192  B_hi  128 rows x 32B
//   +12288 B_lo
#define STG 16384

__global__ void __launch_bounds__(256, 2)
gemm_hmma_kernel(const float* __restrict__ A,    // x (B, K) row-major
                 const float* __restrict__ W,    // pooler_w (S', K) row-major
                 const float* __restrict__ clsw) {
    __shared__ __align__(1024) char smem[2 * STG];
    const uint32_t sb = smem_u32(smem);

    const int tid  = threadIdx.x;
    const int lane = tid & 31;
    const int wid  = tid >> 5;
    const int g    = lane >> 2;    // group
    const int t4   = lane & 3;
    const int wm   = (wid & 3) * 32;    // warp M offset in tile
    const int wn   = (wid >> 2) * 64;   // warp N offset in tile
    const int bB   = blockIdx.y * BM;
    const int bS   = blockIdx.x * BN;

    // producer: this thread owns rows r0 = tid/4 and r0+64, col-quad c4 = tid%4 (both A and B)
    const int prow = tid >> 2;
    const int pc4  = tid & 3;
    const float* pa0 = A + (size_t)(bB + prow) * SDIM + pc4 * 4;
    const float* pa1 = A + (size_t)(bB + prow + 64) * SDIM + pc4 * 4;
    const float* pb0 = W + (size_t)(bS + prow) * SDIM + pc4 * 4;
    const float* pb1 = W + (size_t)(bS + prow + 64) * SDIM + pc4 * 4;
    const uint32_t soff0 = swz((uint32_t)(prow * 32 + pc4 * 8));
    const uint32_t soff1 = swz((uint32_t)((prow + 64) * 32 + pc4 * 8));

    // ldmatrix source offsets (constant per thread)
    uint32_t offAm[2], offBn[4];
    {
        int r = lane & 15, kc = lane >> 4;
        #pragma unroll
        for (int mt = 0; mt < 2; ++mt)
            offAm[mt] = swz((uint32_t)((wm + mt * 16 + r) * 32 + kc * 16));
        int rb = (lane & 7) + ((lane >> 4) << 3), kcb = (lane >> 3) & 1;
        #pragma unroll
        for (int np = 0; np < 4; ++np)
            offBn[np] = swz((uint32_t)((wn + np * 16 + rb) * 32 + kcb * 16));
    }

    float acc[2][8][4];
    #pragma unroll
    for (int mt = 0; mt < 2; ++mt)
        #pragma unroll
        for (int nt = 0; nt < 8; ++nt)
            #pragma unroll
            for (int c = 0; c < 4; ++c) acc[mt][nt][c] = 0.0f;

    // prologue: chunk 0
    {
        float4 va0 = *(const float4*)pa0;
        float4 va1 = *(const float4*)pa1;
        float4 vb0 = *(const float4*)pb0;
        float4 vb1 = *(const float4*)pb1;
        split_store(smem + 0,    smem + 4096,  soff0, va0);
        split_store(smem + 0,    smem + 4096,  soff1, va1);
        split_store(smem + 8192, smem + 12288, soff0, vb0);
        split_store(smem + 8192, smem + 12288, soff1, vb1);
    }
    __syncthreads();

    #pragma unroll 1
    for (int ch = 0; ch < NCH; ++ch) {
        const int st = ch & 1;
        const uint32_t stb = sb + st * STG;

        float4 va0, va1, vb0, vb1;
        const bool more = (ch + 1 < NCH);
        if (more) {
            int ko = (ch + 1) * BK;
            va0 = *(const float4*)(pa0 + ko);
            va1 = *(const float4*)(pa1 + ko);
            vb0 = *(const float4*)(pb0 + ko);
            vb1 = *(const float4*)(pb1 + ko);
        }

        // load A fragments (hi + lo)
        uint32_t aH[2][4], aL[2][4];
        #pragma unroll
        for (int mt = 0; mt < 2; ++mt) {
            LDSM_X4(aH[mt][0], aH[mt][1], aH[mt][2], aH[mt][3], stb + offAm[mt]);
            LDSM_X4(aL[mt][0], aL[mt][1], aL[mt][2], aL[mt][3], stb + 4096 + offAm[mt]);
        }
        // B pairs + MMAs
        #pragma unroll
        for (int np = 0; np < 4; ++np) {
            uint32_t bH[4], bL[4];
            LDSM_X4(bH[0], bH[1], bH[2], bH[3], stb + 8192  + offBn[np]);
            LDSM_X4(bL[0], bL[1], bL[2], bL[3], stb + 12288 + offBn[np]);
            #pragma unroll
            for (int mt = 0; mt < 2; ++mt) {
                #pragma unroll
                for (int j = 0; j < 2; ++j) {
                    float* c = acc[mt][np * 2 + j];
                    mma16816(c, aH[mt][0], aH[mt][1], aH[mt][2], aH[mt][3], bH[2*j], bH[2*j+1]);
                    mma16816(c, aH[mt][0], aH[mt][1], aH[mt][2], aH[mt][3], bL[2*j], bL[2*j+1]);
                    mma16816(c, aL[mt][0], aL[mt][1], aL[mt][2], aL[mt][3], bH[2*j], bH[2*j+1]);
                }
            }
        }
        __syncthreads();   // all warps done reading stage st^1's previous contents
        if (more) {
            char* nb = smem + (st ^ 1) * STG;
            split_store(nb + 0,    nb + 4096,  soff0, va0);
            split_store(nb + 0,    nb + 4096,  soff1, va1);
            split_store(nb + 8192, nb + 12288, soff0, vb0);
            split_store(nb + 8192, nb + 12288, soff1, vb1);
        }
        __syncthreads();   // stage st^1 filled before next chunk reads it
    }

    // ---------------- fused epilogue ----------------
    // rowsum over this warp's 64 columns for its 32 rows
    float rs[4] = {0.0f, 0.0f, 0.0f, 0.0f};   // (mt*2 + half)
    #pragma unroll
    for (int nt = 0; nt < 8; ++nt) {
        int col0 = bS + wn + nt * 8 + 2 * t4;
        float d0 = g_d[col0],     w0 = clsw[col0];
        float d1 = g_d[col0 + 1], w1 = clsw[col0 + 1];
        #pragma unroll
        for (int mt = 0; mt < 2; ++mt) {
            rs[mt * 2 + 0] += gelu_exact(acc[mt][nt][0] + d0) * w0
                            + gelu_exact(acc[mt][nt][1] + d1) * w1;
            rs[mt * 2 + 1] += gelu_exact(acc[mt][nt][2] + d0) * w0
                            + gelu_exact(acc[mt][nt][3] + d1) * w1;
        }
    }
    #pragma unroll
    for (int o = 1; o <= 2; o <<= 1) {
        #pragma unroll
        for (int i = 0; i < 4; ++i) rs[i] += __shfl_xor_sync(0xffffffffu, rs[i], o);
    }

    float* redbuf = (float*)smem;   // [2][128], reuse stage memory
    __syncthreads();                // all compute done before smem reuse
    if (t4 == 0) {
        #pragma unroll
        for (int mt = 0; mt < 2; ++mt) {
            #pragma unroll
            for (int h = 0; h < 2; ++h) {
                int row = wm + mt * 16 + h * 8 + g;
                redbuf[(wid >> 2) * 128 + row] = rs[mt * 2 + h];
            }
        }
    }
    __syncthreads();
    if (tid < 128) {
        float p = redbuf[tid] + redbuf[128 + tid];
        g_partial[(size_t)(bB + tid) * NTILE + blockIdx.x] = p;
    }
}

__global__ void final_kernel(const float* __restrict__ cls_b, float* __restrict__ out) {
    int b = blockIdx.x * blockDim.x + threadIdx.x;
    if (b < BDIM) {
        float sum = 0.0f;
        #pragma unroll
        for (int j = 0; j < NTILE; ++j) sum += g_partial[(size_t)b * NTILE + j];
        out[b] = sum + cls_b[0];
    }
}

// ---------------- launch ----------------
extern "C" void kernel_launch(void* const* d_in, const int* in_sizes, int n_in,
                              void* d_out, int out_size) {
    const float* x          = (const float*)d_in[0];
    const float* ln1_b      = (const float*)d_in[2];
    const float* cp1_w      = (const float*)d_in[3];
    const float* cp1_b      = (const float*)d_in[4];
    const float* sgu_ln_b   = (const float*)d_in[6];
    const float* sgu_proj_w = (const float*)d_in[7];
    const float* sgu_proj_b = (const float*)d_in[8];
    const float* cp2_w      = (const float*)d_in[9];
    const float* cp2_b      = (const float*)d_in[10];
    const float* pooler_w   = (const float*)d_in[11];
    const float* pooler_b   = (const float*)d_in[12];
    const float* cls_w      = (const float*)d_in[13];
    const float* cls_b      = (const float*)d_in[14];

    compute_c_kernel<<<SDIM, 256>>>(sgu_proj_w, sgu_proj_b, ln1_b, cp1_w, cp1_b,
                                    sgu_ln_b, cp2_w, cp2_b);
    compute_d_kernel<<<SDIM, 256>>>(pooler_w, pooler_b);

    dim3 grid(SDIM / BN, BDIM / BM);   // (32, 32)
    gemm_hmma_kernel<<<grid, 256>>>(x, pooler_w, cls_w);

    final_kernel<<<(BDIM + 255) / 256, 256>>>(cls_b, (float*)d_out);
}